// round 3
// baseline (speedup 1.0000x reference)
#include <cuda_runtime.h>
#include <math.h>

// Problem constants
#define TOKENS   65536          // 64 * 32 * 32
#define DDIM     256
#define KCODES   4096
#define HW       1024           // 32*32
#define BM       128            // tokens per CTA
#define BN       128            // codes per tile
#define BK       32             // D-chunk per inner tile
#define APAD     132            // padded leading dim for smem tiles
#define NB1      (TOKENS / BM)  // 512 CTAs
#define OUT_ELEMS 16777216      // 64*256*32*32

// Scratch (no allocation allowed -> device globals)
__device__ float g_enorm2[KCODES];
__device__ int   g_idx[TOKENS];
__device__ float g_partial[NB1];
__device__ int   g_counts[KCODES];

// ---------------------------------------------------------------------------
// Kernel 0: per-code squared norms (fp32, like reference's sum(emb*emb)) + zero hist
// ---------------------------------------------------------------------------
__global__ void k_prep(const float* __restrict__ emb) {
    int row = blockIdx.x;
    float v = emb[(size_t)row * DDIM + threadIdx.x];
    float s = v * v;
    __shared__ float red[8];
    #pragma unroll
    for (int o = 16; o > 0; o >>= 1) s += __shfl_down_sync(0xffffffffu, s, o);
    if ((threadIdx.x & 31) == 0) red[threadIdx.x >> 5] = s;
    __syncthreads();
    if (threadIdx.x == 0) {
        float t = 0.f;
        #pragma unroll
        for (int i = 0; i < 8; i++) t += red[i];
        g_enorm2[row] = t;
        g_counts[row] = 0;
    }
}

// ---------------------------------------------------------------------------
// Kernel 1: fused distance GEMM + quantized argmin (reference-exact rounding)
//   d(n,k) = fl( fl(xn2_n + en2_k) - 2 * dot(n,k) )   [matches a+b-2m chain]
//   argmin ties broken by LOWEST code index (packed u64 compare).
// ---------------------------------------------------------------------------
__global__ void __launch_bounds__(256, 1)
k_argmin(const float* __restrict__ x, const float* __restrict__ emb) {
    extern __shared__ float sm[];
    float* As = sm;                        // DDIM * APAD floats (A[d][m])
    float* Bs = sm + DDIM * APAD;          // BK * APAD floats   (B[k][n])
    float* sen = Bs + BK * APAD;           // KCODES floats (|e_k|^2)
    __shared__ float sxn2[BM];

    const int t    = threadIdx.x;
    const int base = blockIdx.x * BM;
    const int b    = base >> 10;
    const int hw0  = base & 1023;
    const float* xb = x + (size_t)b * (DDIM * HW) + hw0;

    // ---- stage |e|^2 table into shared ----
    #pragma unroll
    for (int i = 0; i < KCODES / 256; i++)
        sen[i * 256 + t] = g_enorm2[i * 256 + t];

    // ---- Load A: As[d*APAD + m] = x[b, d, hw0+m], coalesced float4 over m ----
    {
        const int lane4 = (t & 31) * 4;
        const int d0    = t >> 5;
        #pragma unroll
        for (int dd = 0; dd < DDIM; dd += 8) {
            int d = dd + d0;
            float4 v = *(const float4*)(xb + (size_t)d * HW + lane4);
            *(float4*)(&As[d * APAD + lane4]) = v;
        }
    }
    __syncthreads();

    // ---- per-token |x_n|^2 (fp32), needed for quantized scores ----
    if (t < BM) {
        float s = 0.f;
        #pragma unroll 8
        for (int d = 0; d < DDIM; d++) {
            float v = As[d * APAD + t];
            s = fmaf(v, v, s);
        }
        sxn2[t] = s;
    }
    __syncthreads();

    const int ty = t >> 4;   // token group 0..15 (rows ty*8 .. ty*8+7)
    const int tx = t & 15;   // code  group 0..15 (cols tx*8 .. tx*8+7)

    float myxn2[8];
    #pragma unroll
    for (int i = 0; i < 8; i++) myxn2[i] = sxn2[ty * 8 + i];

    float best[8];
    int   bidx[8];
    #pragma unroll
    for (int i = 0; i < 8; i++) { best[i] = 3.4e38f; bidx[i] = 0; }

    for (int c0 = 0; c0 < KCODES; c0 += BN) {
        float acc[8][8];
        #pragma unroll
        for (int i = 0; i < 8; i++)
            #pragma unroll
            for (int j = 0; j < 8; j++) acc[i][j] = 0.f;

        for (int d0 = 0; d0 < DDIM; d0 += BK) {
            float4 breg[4];
            #pragma unroll
            for (int it = 0; it < 4; it++) {
                int linear = it * 256 + t;
                int row = linear >> 3;
                int dq  = linear & 7;
                breg[it] = *(const float4*)(emb + (size_t)(c0 + row) * DDIM + d0 + dq * 4);
            }
            __syncthreads();
            #pragma unroll
            for (int it = 0; it < 4; it++) {
                int linear = it * 256 + t;
                int row = linear >> 3;
                int dq  = linear & 7;
                Bs[(dq * 4 + 0) * APAD + row] = breg[it].x;
                Bs[(dq * 4 + 1) * APAD + row] = breg[it].y;
                Bs[(dq * 4 + 2) * APAD + row] = breg[it].z;
                Bs[(dq * 4 + 3) * APAD + row] = breg[it].w;
            }
            __syncthreads();

            #pragma unroll
            for (int k = 0; k < BK; k++) {
                float a[8], bb[8];
                float4 av0 = *(float4*)&As[(d0 + k) * APAD + ty * 8];
                float4 av1 = *(float4*)&As[(d0 + k) * APAD + ty * 8 + 4];
                float4 bv0 = *(float4*)&Bs[k * APAD + tx * 8];
                float4 bv1 = *(float4*)&Bs[k * APAD + tx * 8 + 4];
                a[0]=av0.x; a[1]=av0.y; a[2]=av0.z; a[3]=av0.w;
                a[4]=av1.x; a[5]=av1.y; a[6]=av1.z; a[7]=av1.w;
                bb[0]=bv0.x; bb[1]=bv0.y; bb[2]=bv0.z; bb[3]=bv0.w;
                bb[4]=bv1.x; bb[5]=bv1.y; bb[6]=bv1.z; bb[7]=bv1.w;
                #pragma unroll
                for (int i = 0; i < 8; i++)
                    #pragma unroll
                    for (int j = 0; j < 8; j++)
                        acc[i][j] = fmaf(a[i], bb[j], acc[i][j]);
            }
        }

        // Fold tile into running argmin with reference-exact rounding:
        //   A = fl(xn2 + en2);  d = fma(-2, dot, A)  == fl(A - 2*dot)
        // Codes scanned in ascending order + strict '<' => lowest-index tie-break.
        #pragma unroll
        for (int j = 0; j < 8; j++) {
            int code = c0 + tx * 8 + j;
            float en = sen[code];
            #pragma unroll
            for (int i = 0; i < 8; i++) {
                float A = myxn2[i] + en;            // rounded fp32 add
                float d = fmaf(-2.f, acc[i][j], A); // single rounding, == A - 2m
                if (d < best[i]) { best[i] = d; bidx[i] = code; }
            }
        }
    }

    // ---- Cross-thread argmin: packed (float bits, code) u64 min ----
    __syncthreads();
    unsigned long long* redp = (unsigned long long*)As;  // 128*16 u64 = 16KB
    #pragma unroll
    for (int i = 0; i < 8; i++) {
        int token = ty * 8 + i;
        unsigned long long p =
            ((unsigned long long)__float_as_uint(best[i]) << 32) | (unsigned)bidx[i];
        redp[token * 16 + tx] = p;
    }
    __syncthreads();

    float part = 0.f;
    if (t < BM) {
        unsigned long long bp = redp[t * 16];
        #pragma unroll
        for (int u = 1; u < 16; u++) {
            unsigned long long p = redp[t * 16 + u];
            if (p < bp) bp = p;
        }
        int   bi = (int)(bp & 0xffffffffu);
        float bv = __uint_as_float((unsigned)(bp >> 32));
        g_idx[base + t] = bi;
        part = bv;            // d* = ||x - e*||^2 (already includes xn2)
    }

    __shared__ float wsum[8];
    #pragma unroll
    for (int o = 16; o > 0; o >>= 1) part += __shfl_down_sync(0xffffffffu, part, o);
    if ((t & 31) == 0) wsum[t >> 5] = part;
    __syncthreads();
    if (t == 0) {
        float s = 0.f;
        #pragma unroll
        for (int i = 0; i < 8; i++) s += wsum[i];
        g_partial[blockIdx.x] = s;
    }
}

// ---------------------------------------------------------------------------
// Kernel 2: gather codebook rows, write transposed output, histogram
// ---------------------------------------------------------------------------
__global__ void __launch_bounds__(256, 1)
k_gather(const float* __restrict__ emb, float* __restrict__ out) {
    extern __shared__ float rows[];      // 128 * 257 floats
    __shared__ int sidx[BM];

    const int t    = threadIdx.x;
    const int base = blockIdx.x * BM;

    if (t < BM) {
        int id = g_idx[base + t];
        sidx[t] = id;
        atomicAdd(&g_counts[id], 1);
    }
    __syncthreads();

    const int w = t >> 5, lane = t & 31;
    for (int r = w; r < BM; r += 8) {
        const float* er = emb + (size_t)sidx[r] * DDIM;
        #pragma unroll
        for (int q = 0; q < 8; q++)
            rows[r * 257 + lane + q * 32] = er[lane + q * 32];
    }
    __syncthreads();

    const int b   = base >> 10;
    const int hw0 = base & 1023;
    float* ob = out + (size_t)b * (DDIM * HW) + hw0;
    const int m  = t & 127;
    const int ch = t >> 7;
    #pragma unroll 4
    for (int cc = 0; cc < 128; cc++) {
        int c = cc * 2 + ch;
        ob[(size_t)c * HW + m] = rows[m * 257 + c];
    }
}

// ---------------------------------------------------------------------------
// Kernel 3: loss reduce + perplexity
// ---------------------------------------------------------------------------
__global__ void k_final(float* __restrict__ out) {
    __shared__ float sh[1024];
    const int t = threadIdx.x;

    float s = (t < NB1) ? g_partial[t] : 0.f;
    sh[t] = s; __syncthreads();
    for (int o = 512; o > 0; o >>= 1) {
        if (t < o) sh[t] += sh[t + o];
        __syncthreads();
    }
    if (t == 0) out[OUT_ELEMS] = 1.25f * sh[0] / 16777216.0f;
    __syncthreads();

    float e = 0.f;
    for (int k = t; k < KCODES; k += 1024) {
        float p = (float)g_counts[k] * (1.0f / 65536.0f);
        e -= p * logf(p + 1e-10f);
    }
    sh[t] = e; __syncthreads();
    for (int o = 512; o > 0; o >>= 1) {
        if (t < o) sh[t] += sh[t + o];
        __syncthreads();
    }
    if (t == 0) out[OUT_ELEMS + 1] = expf(sh[0]);
}

// ---------------------------------------------------------------------------
extern "C" void kernel_launch(void* const* d_in, const int* in_sizes, int n_in,
                              void* d_out, int out_size) {
    const float* x   = (const float*)d_in[0];
    const float* emb = (const float*)d_in[1];
    float* out = (float*)d_out;

    const int SMEM1 = (DDIM * APAD + BK * APAD + KCODES) * sizeof(float); // ~168 KB
    const int SMEM2 = BM * 257 * sizeof(float);                           // ~132 KB
    cudaFuncSetAttribute(k_argmin, cudaFuncAttributeMaxDynamicSharedMemorySize, SMEM1);
    cudaFuncSetAttribute(k_gather, cudaFuncAttributeMaxDynamicSharedMemorySize, SMEM2);

    k_prep  <<<KCODES, 256>>>(emb);
    k_argmin<<<NB1,    256, SMEM1>>>(x, emb);
    k_gather<<<NB1,    256, SMEM2>>>(emb, out);
    k_final <<<1,     1024>>>(out);
}

// round 4
// speedup vs baseline: 1.0262x; 1.0262x over previous
#include <cuda_runtime.h>
#include <math.h>

// Problem constants
#define TOKENS   65536          // 64 * 32 * 32
#define DDIM     256
#define KCODES   4096
#define HW       1024           // 32*32
#define BM       128            // tokens per CTA
#define BN       128            // codes per tile
#define BK       32             // D-chunk per inner tile
#define APAD     132            // padded leading dim for smem tiles
#define NB1      (TOKENS / BM)  // 512 CTAs
#define OUT_ELEMS 16777216      // 64*256*32*32

// Packed fp32x2 FMA (Blackwell FFMA2) — exact fp32 per component, 2x FFMA rate.
#define FMA_F32X2(d, a, b, c) \
    asm("fma.rn.f32x2 %0, %1, %2, %3;" : "=l"(d) : "l"(a), "l"(b), "l"(c))
#define PACK2(out, xu, yu) \
    asm("mov.b64 %0, {%1, %2};" : "=l"(out) : "r"(xu), "r"(yu))
#define UNPACK2(lo, hi, in) \
    asm("mov.b64 {%0, %1}, %2;" : "=r"(lo), "=r"(hi) : "l"(in))

// Scratch (no allocation allowed -> device globals)
__device__ float g_enorm2[KCODES];
__device__ int   g_idx[TOKENS];
__device__ float g_partial[NB1];
__device__ int   g_counts[KCODES];

// ---------------------------------------------------------------------------
// Kernel 0: per-code squared norms + zero histogram
// ---------------------------------------------------------------------------
__global__ void k_prep(const float* __restrict__ emb) {
    int row = blockIdx.x;
    float v = emb[(size_t)row * DDIM + threadIdx.x];
    float s = v * v;
    __shared__ float red[8];
    #pragma unroll
    for (int o = 16; o > 0; o >>= 1) s += __shfl_down_sync(0xffffffffu, s, o);
    if ((threadIdx.x & 31) == 0) red[threadIdx.x >> 5] = s;
    __syncthreads();
    if (threadIdx.x == 0) {
        float t = 0.f;
        #pragma unroll
        for (int i = 0; i < 8; i++) t += red[i];
        g_enorm2[row] = t;
        g_counts[row] = 0;
    }
}

// ---------------------------------------------------------------------------
// Kernel 1: fused distance GEMM (packed FFMA2) + quantized argmin
//   d(n,k) = fl( fl(xn2_n + en2_k) - 2 * dot(n,k) )   [reference-exact chain]
//   argmin ties broken by LOWEST code index (packed u64 compare).
// ---------------------------------------------------------------------------
__global__ void __launch_bounds__(256, 1)
k_argmin(const float* __restrict__ x, const float* __restrict__ emb) {
    extern __shared__ float sm[];
    float* As = sm;                        // DDIM * APAD floats (A[d][m])
    float* Bs = sm + DDIM * APAD;          // BK * APAD floats   (B[k][n])
    float* sen = Bs + BK * APAD;           // KCODES floats (|e_k|^2)
    __shared__ float sxn2[BM];

    const int t    = threadIdx.x;
    const int base = blockIdx.x * BM;
    const int b    = base >> 10;
    const int hw0  = base & 1023;
    const float* xb = x + (size_t)b * (DDIM * HW) + hw0;

    // ---- stage |e|^2 table into shared ----
    #pragma unroll
    for (int i = 0; i < KCODES / 256; i++)
        sen[i * 256 + t] = g_enorm2[i * 256 + t];

    // ---- Load A: As[d*APAD + m] = x[b, d, hw0+m], coalesced float4 over m ----
    {
        const int lane4 = (t & 31) * 4;
        const int d0    = t >> 5;
        #pragma unroll
        for (int dd = 0; dd < DDIM; dd += 8) {
            int d = dd + d0;
            float4 v = *(const float4*)(xb + (size_t)d * HW + lane4);
            *(float4*)(&As[d * APAD + lane4]) = v;
        }
    }
    __syncthreads();

    // ---- per-token |x_n|^2 (fp32) ----
    if (t < BM) {
        float s = 0.f;
        #pragma unroll 8
        for (int d = 0; d < DDIM; d++) {
            float v = As[d * APAD + t];
            s = fmaf(v, v, s);
        }
        sxn2[t] = s;
    }
    __syncthreads();

    const int ty = t >> 4;   // token group 0..15 (rows ty*8 .. ty*8+7)
    const int tx = t & 15;   // code  group 0..15 (cols tx*8 .. tx*8+7)

    float myxn2[8];
    #pragma unroll
    for (int i = 0; i < 8; i++) myxn2[i] = sxn2[ty * 8 + i];

    float best[8];
    int   bidx[8];
    #pragma unroll
    for (int i = 0; i < 8; i++) { best[i] = 3.4e38f; bidx[i] = 0; }

    for (int c0 = 0; c0 < KCODES; c0 += BN) {
        // packed accumulators: acc2[i][j2] holds codes (tx*8+2*j2, tx*8+2*j2+1)
        unsigned long long acc2[8][4];
        #pragma unroll
        for (int i = 0; i < 8; i++)
            #pragma unroll
            for (int j2 = 0; j2 < 4; j2++) acc2[i][j2] = 0ULL;

        for (int d0 = 0; d0 < DDIM; d0 += BK) {
            float4 breg[4];
            #pragma unroll
            for (int it = 0; it < 4; it++) {
                int linear = it * 256 + t;
                int row = linear >> 3;
                int dq  = linear & 7;
                breg[it] = *(const float4*)(emb + (size_t)(c0 + row) * DDIM + d0 + dq * 4);
            }
            __syncthreads();
            #pragma unroll
            for (int it = 0; it < 4; it++) {
                int linear = it * 256 + t;
                int row = linear >> 3;
                int dq  = linear & 7;
                Bs[(dq * 4 + 0) * APAD + row] = breg[it].x;
                Bs[(dq * 4 + 1) * APAD + row] = breg[it].y;
                Bs[(dq * 4 + 2) * APAD + row] = breg[it].z;
                Bs[(dq * 4 + 3) * APAD + row] = breg[it].w;
            }
            __syncthreads();

            #pragma unroll
            for (int k = 0; k < BK; k++) {
                float4 av0 = *(float4*)&As[(d0 + k) * APAD + ty * 8];
                float4 av1 = *(float4*)&As[(d0 + k) * APAD + ty * 8 + 4];
                float4 bv0 = *(float4*)&Bs[k * APAD + tx * 8];
                float4 bv1 = *(float4*)&Bs[k * APAD + tx * 8 + 4];

                // b pairs: adjacent codes packed into u64
                unsigned long long b2[4];
                PACK2(b2[0], __float_as_uint(bv0.x), __float_as_uint(bv0.y));
                PACK2(b2[1], __float_as_uint(bv0.z), __float_as_uint(bv0.w));
                PACK2(b2[2], __float_as_uint(bv1.x), __float_as_uint(bv1.y));
                PACK2(b2[3], __float_as_uint(bv1.z), __float_as_uint(bv1.w));

                // a broadcast pairs
                float a[8];
                a[0]=av0.x; a[1]=av0.y; a[2]=av0.z; a[3]=av0.w;
                a[4]=av1.x; a[5]=av1.y; a[6]=av1.z; a[7]=av1.w;
                unsigned long long a2[8];
                #pragma unroll
                for (int i = 0; i < 8; i++) {
                    unsigned au = __float_as_uint(a[i]);
                    PACK2(a2[i], au, au);
                }

                #pragma unroll
                for (int i = 0; i < 8; i++)
                    #pragma unroll
                    for (int j2 = 0; j2 < 4; j2++)
                        FMA_F32X2(acc2[i][j2], a2[i], b2[j2], acc2[i][j2]);
            }
        }

        // Unpack and fold into running argmin (reference-exact rounding):
        //   A = fl(xn2 + en2);  d = fma(-2, dot, A)  == fl(A - 2m)
        #pragma unroll
        for (int j2 = 0; j2 < 4; j2++) {
            int code0 = c0 + tx * 8 + 2 * j2;
            float en0 = sen[code0];
            float en1 = sen[code0 + 1];
            #pragma unroll
            for (int i = 0; i < 8; i++) {
                unsigned lo, hi;
                UNPACK2(lo, hi, acc2[i][j2]);
                float m0 = __uint_as_float(lo);
                float m1 = __uint_as_float(hi);
                float A0 = myxn2[i] + en0;
                float A1 = myxn2[i] + en1;
                float d0v = fmaf(-2.f, m0, A0);
                float d1v = fmaf(-2.f, m1, A1);
                if (d0v < best[i]) { best[i] = d0v; bidx[i] = code0; }
                if (d1v < best[i]) { best[i] = d1v; bidx[i] = code0 + 1; }
            }
        }
    }

    // ---- Cross-thread argmin: packed (float bits, code) u64 min ----
    __syncthreads();
    unsigned long long* redp = (unsigned long long*)As;  // 128*16 u64 = 16KB
    #pragma unroll
    for (int i = 0; i < 8; i++) {
        int token = ty * 8 + i;
        unsigned long long p =
            ((unsigned long long)__float_as_uint(best[i]) << 32) | (unsigned)bidx[i];
        redp[token * 16 + tx] = p;
    }
    __syncthreads();

    float part = 0.f;
    if (t < BM) {
        unsigned long long bp = redp[t * 16];
        #pragma unroll
        for (int u = 1; u < 16; u++) {
            unsigned long long p = redp[t * 16 + u];
            if (p < bp) bp = p;
        }
        int   bi = (int)(bp & 0xffffffffu);
        float bv = __uint_as_float((unsigned)(bp >> 32));
        g_idx[base + t] = bi;
        part = bv;            // d* = ||x - e*||^2
    }

    __shared__ float wsum[8];
    #pragma unroll
    for (int o = 16; o > 0; o >>= 1) part += __shfl_down_sync(0xffffffffu, part, o);
    if ((t & 31) == 0) wsum[t >> 5] = part;
    __syncthreads();
    if (t == 0) {
        float s = 0.f;
        #pragma unroll
        for (int i = 0; i < 8; i++) s += wsum[i];
        g_partial[blockIdx.x] = s;
    }
}

// ---------------------------------------------------------------------------
// Kernel 2: gather codebook rows, write transposed output, histogram
// ---------------------------------------------------------------------------
__global__ void __launch_bounds__(256, 1)
k_gather(const float* __restrict__ emb, float* __restrict__ out) {
    extern __shared__ float rows[];      // 128 * 257 floats
    __shared__ int sidx[BM];

    const int t    = threadIdx.x;
    const int base = blockIdx.x * BM;

    if (t < BM) {
        int id = g_idx[base + t];
        sidx[t] = id;
        atomicAdd(&g_counts[id], 1);
    }
    __syncthreads();

    const int w = t >> 5, lane = t & 31;
    for (int r = w; r < BM; r += 8) {
        const float* er = emb + (size_t)sidx[r] * DDIM;
        #pragma unroll
        for (int q = 0; q < 8; q++)
            rows[r * 257 + lane + q * 32] = er[lane + q * 32];
    }
    __syncthreads();

    const int b   = base >> 10;
    const int hw0 = base & 1023;
    float* ob = out + (size_t)b * (DDIM * HW) + hw0;
    const int m  = t & 127;
    const int ch = t >> 7;
    #pragma unroll 4
    for (int cc = 0; cc < 128; cc++) {
        int c = cc * 2 + ch;
        ob[(size_t)c * HW + m] = rows[m * 257 + c];
    }
}

// ---------------------------------------------------------------------------
// Kernel 3: loss reduce + perplexity
// ---------------------------------------------------------------------------
__global__ void k_final(float* __restrict__ out) {
    __shared__ float sh[1024];
    const int t = threadIdx.x;

    float s = (t < NB1) ? g_partial[t] : 0.f;
    sh[t] = s; __syncthreads();
    for (int o = 512; o > 0; o >>= 1) {
        if (t < o) sh[t] += sh[t + o];
        __syncthreads();
    }
    if (t == 0) out[OUT_ELEMS] = 1.25f * sh[0] / 16777216.0f;
    __syncthreads();

    float e = 0.f;
    for (int k = t; k < KCODES; k += 1024) {
        float p = (float)g_counts[k] * (1.0f / 65536.0f);
        e -= p * logf(p + 1e-10f);
    }
    sh[t] = e; __syncthreads();
    for (int o = 512; o > 0; o >>= 1) {
        if (t < o) sh[t] += sh[t + o];
        __syncthreads();
    }
    if (t == 0) out[OUT_ELEMS + 1] = expf(sh[0]);
}

// ---------------------------------------------------------------------------
extern "C" void kernel_launch(void* const* d_in, const int* in_sizes, int n_in,
                              void* d_out, int out_size) {
    const float* x   = (const float*)d_in[0];
    const float* emb = (const float*)d_in[1];
    float* out = (float*)d_out;

    const int SMEM1 = (DDIM * APAD + BK * APAD + KCODES) * sizeof(float); // ~168 KB
    const int SMEM2 = BM * 257 * sizeof(float);                           // ~132 KB
    cudaFuncSetAttribute(k_argmin, cudaFuncAttributeMaxDynamicSharedMemorySize, SMEM1);
    cudaFuncSetAttribute(k_gather, cudaFuncAttributeMaxDynamicSharedMemorySize, SMEM2);

    k_prep  <<<KCODES, 256>>>(emb);
    k_argmin<<<NB1,    256, SMEM1>>>(x, emb);
    k_gather<<<NB1,    256, SMEM2>>>(emb, out);
    k_final <<<1,     1024>>>(out);
}